// round 1
// baseline (speedup 1.0000x reference)
#include <cuda_runtime.h>
#include <math_constants.h>

#define NQ 1024
#define NK 2048
#define D  64

// Scratch (no allocs allowed in kernel_launch)
__device__ float g_qp [NQ * D];   // qp[q][h]
__device__ float g_kpb[NK * D];   // kp[k][h] + b1[h]
__device__ float g_vt [NK * D];   // value transposed: vt[k][d]
__device__ float g_rmax[NQ];
__device__ float g_rinv[NQ];      // 1 / sum(exp(s - max))

// ---------------------------------------------------------------------------
// Kernel 1: projections.  blocks [0,NQ) -> qp column q ; [NQ,NQ+NK) -> kpb col k
// 64 threads per block, thread t = output feature h.
// ---------------------------------------------------------------------------
__global__ void k_proj(const float* __restrict__ query,
                       const float* __restrict__ key,
                       const float* __restrict__ W1,
                       const float* __restrict__ b1)
{
    __shared__ float col[D];
    __shared__ float Ws[D][D + 1];

    int b = blockIdx.x;
    int t = threadIdx.x;                 // h
    bool isQ = (b < NQ);
    int c = isQ ? b : (b - NQ);
    const float* src = isQ ? query : key;
    int stride = isQ ? NQ : NK;
    int wofs = isQ ? 0 : D;

    col[t] = src[t * stride + c];
    for (int i = t; i < D * D; i += 64) {
        int h = i >> 6, d = i & 63;
        Ws[h][d] = W1[h * (2 * D) + wofs + d];
    }
    __syncthreads();

    float acc = isQ ? 0.0f : b1[t];
    #pragma unroll 16
    for (int d = 0; d < D; d++) acc += Ws[t][d] * col[d];

    float* dst = isQ ? (g_qp + c * D) : (g_kpb + c * D);
    dst[t] = acc;
}

// ---------------------------------------------------------------------------
// Kernel 1b: transpose value [d][k] -> vt[k][d]
// ---------------------------------------------------------------------------
__global__ void k_transpose(const float* __restrict__ value)
{
    int idx = blockIdx.x * blockDim.x + threadIdx.x;   // over NK*D
    if (idx >= NK * D) return;
    int k = idx >> 6, d = idx & 63;
    g_vt[idx] = value[d * NK + k];
}

// ---------------------------------------------------------------------------
// Kernel 2: scores[q][k] = sum_h W2[h]*relu(qp[q][h]+kpb[k][h]) + b2
// Block: 64q x 64k tile, 256 threads, each thread 4x4.
// ---------------------------------------------------------------------------
__global__ void k_scores(const float* __restrict__ W2,
                         const float* __restrict__ b2,
                         float* __restrict__ scores)
{
    __shared__ float qs[64][65];
    __shared__ float ks[64][65];
    __shared__ float w2s[64];

    int qbase = blockIdx.x * 64;
    int kbase = blockIdx.y * 64;
    int tid = threadIdx.x;

    for (int i = tid; i < 64 * 64; i += 256) {
        int r = i >> 6, c = i & 63;
        qs[r][c] = g_qp [(qbase + r) * D + c];
        ks[r][c] = g_kpb[(kbase + r) * D + c];
    }
    if (tid < 64) w2s[tid] = W2[tid];
    __syncthreads();

    int tx = tid & 15;       // k sub-index
    int ty = tid >> 4;       // q sub-index

    float acc[4][4];
    #pragma unroll
    for (int i = 0; i < 4; i++)
        #pragma unroll
        for (int j = 0; j < 4; j++) acc[i][j] = 0.0f;

    #pragma unroll 8
    for (int h = 0; h < 64; h++) {
        float w = w2s[h];
        float a[4], bb[4];
        #pragma unroll
        for (int i = 0; i < 4; i++) a[i] = qs[ty + 16 * i][h];
        #pragma unroll
        for (int j = 0; j < 4; j++) bb[j] = ks[tx + 16 * j][h];
        #pragma unroll
        for (int i = 0; i < 4; i++)
            #pragma unroll
            for (int j = 0; j < 4; j++)
                acc[i][j] += w * fmaxf(a[i] + bb[j], 0.0f);
    }

    float bias = b2[0];
    #pragma unroll
    for (int i = 0; i < 4; i++) {
        int q = qbase + ty + 16 * i;
        #pragma unroll
        for (int j = 0; j < 4; j++) {
            int k = kbase + tx + 16 * j;
            scores[q * NK + k] = acc[i][j] + bias;
        }
    }
}

// ---------------------------------------------------------------------------
// Kernel 3: per-row softmax stats (max, 1/sum). One block per q row.
// ---------------------------------------------------------------------------
__global__ void k_stats(const float* __restrict__ scores)
{
    __shared__ float red[256];
    int q = blockIdx.x;
    int t = threadIdx.x;
    const float* row = scores + q * NK;

    float m = -CUDART_INF_F;
    for (int k = t; k < NK; k += 256) m = fmaxf(m, row[k]);
    red[t] = m;
    __syncthreads();
    for (int s = 128; s > 0; s >>= 1) {
        if (t < s) red[t] = fmaxf(red[t], red[t + s]);
        __syncthreads();
    }
    m = red[0];
    __syncthreads();

    float sum = 0.0f;
    for (int k = t; k < NK; k += 256) sum += __expf(row[k] - m);
    red[t] = sum;
    __syncthreads();
    for (int s = 128; s > 0; s >>= 1) {
        if (t < s) red[t] += red[t + s];
        __syncthreads();
    }
    if (t == 0) {
        g_rmax[q] = m;
        g_rinv[q] = 1.0f / red[0];
    }
}

// ---------------------------------------------------------------------------
// Kernel 4: out[d][q] = sum_k p[q][k] * vt[k][d],  p = exp(s-m)*invZ on the fly.
// Block: 8 q's, 256 threads = 8 warps, warp w owns q = qbase + w.
// K-tiles of 128; value tile in smem, p tile in smem.
// ---------------------------------------------------------------------------
__global__ void k_pv(const float* __restrict__ scores,
                     float* __restrict__ out)
{
    __shared__ float vs[128][64];       // vs[kk][d]
    __shared__ float ps[128][9];        // ps[kk][qq], pad 9 (gcd(9,32)=1)

    int qbase = blockIdx.x * 8;
    int tid = threadIdx.x;
    int w = tid >> 5, lane = tid & 31;
    int q = qbase + w;

    float m = g_rmax[q];
    float invz = g_rinv[q];

    float acc0 = 0.0f, acc1 = 0.0f;     // d = 2*lane, 2*lane+1

    for (int kt = 0; kt < NK; kt += 128) {
        __syncthreads();
        // load V tile: 128 x 64 floats via float4 (2048 float4 / 256 thr = 8 ea)
        for (int i = tid; i < (128 * 64) / 4; i += 256) {
            int e = 4 * i;
            int kk = e >> 6, d = e & 63;
            *(float4*)&vs[kk][d] = *(const float4*)&g_vt[(kt + kk) * D + d];
        }
        // p tile: 8 q rows x 128 k, coalesced reads of scores
        for (int i = tid; i < 8 * 128; i += 256) {
            int qq = i >> 7, kk = i & 127;
            int qg = qbase + qq;
            ps[kk][qq] = __expf(scores[qg * NK + kt + kk] - g_rmax[qg]) * g_rinv[qg];
        }
        __syncthreads();

        #pragma unroll 8
        for (int kk = 0; kk < 128; kk++) {
            float p = ps[kk][w];
            float2 v = *(float2*)&vs[kk][2 * lane];
            acc0 += p * v.x;
            acc1 += p * v.y;
        }
    }

    // out layout: [d][q], d-major
    out[(2 * lane    ) * NQ + q] = acc0;
    out[(2 * lane + 1) * NQ + q] = acc1;
    (void)m; (void)invz;
}

// ---------------------------------------------------------------------------
extern "C" void kernel_launch(void* const* d_in, const int* in_sizes, int n_in,
                              void* d_out, int out_size)
{
    const float* query = (const float*)d_in[0];   // [64,1024]
    const float* key   = (const float*)d_in[1];   // [64,2048]
    const float* value = (const float*)d_in[2];   // [64,2048]
    const float* W1    = (const float*)d_in[3];   // [64,128]
    const float* b1    = (const float*)d_in[4];   // [64]
    const float* W2    = (const float*)d_in[5];   // [1,64]
    const float* b2    = (const float*)d_in[6];   // [1]

    float* out_p    = (float*)d_out;                  // [64,1024]
    float* scores_p = (float*)d_out + NQ * D;         // [1024,2048]

    k_proj<<<NQ + NK, 64>>>(query, key, W1, b1);
    k_transpose<<<(NK * D + 255) / 256, 256>>>(value);

    dim3 gs(NQ / 64, NK / 64);
    k_scores<<<gs, 256>>>(W2, b2, scores_p);

    k_stats<<<NQ, 256>>>(scores_p);

    k_pv<<<NQ / 8, 256>>>(scores_p, out_p);
}